// round 2
// baseline (speedup 1.0000x reference)
#include <cuda_runtime.h>
#include <math.h>

// ---------------------------------------------------------------------------
// RolloutModule: 64-step closed-loop MLP policy rollout + STREL robustness.
// One CTA = 64 agents, runs all 64 steps privately (agents independent).
// fp32 baseline: register-blocked 8x8 GEMM tiles, activations in smem
// neuron-major [k][m], weights W2/W3 streamed from L2 in 16-row tiles with
// register prefetch. Online (streaming) stable logsumexp for the temporal
// reductions so no trajectory is stored.
// ---------------------------------------------------------------------------

#define NT   256     // threads per CTA
#define AG   64      // agents per CTA
#define HD   256     // hidden size
#define TK   16      // k-tile rows for streamed W2/W3
#define NSTEP 64

struct __align__(16) Smem {
    float Hbuf[HD * AG];     // activations, [n][m] neuron-major  (64 KB)
    float Obs[16 * AG];      // observation,  [k][m], 13 rows used (4 KB)
    float Wt[TK * HD];       // streamed weight tile [k][n]       (16 KB)
    float W1s[13 * HD];      // resident layer-1 weights          (13 KB)
    float b1s[HD];
    float b2s[HD];
    float b3s[HD];
    float wmuT[2 * HD];      // output weights transposed [d][k]
    float bmus[4];
    float act[2 * AG];       // actions [d][m]
};

__device__ __forceinline__ float clampf(float v, float lo, float hi) {
    return fminf(fmaxf(v, lo), hi);
}

__global__ __launch_bounds__(NT, 2)
void rollout_kernel(const float* __restrict__ pos0,
                    const float* __restrict__ wind,
                    const float* __restrict__ w1, const float* __restrict__ b1,
                    const float* __restrict__ w2, const float* __restrict__ b2,
                    const float* __restrict__ w3, const float* __restrict__ b3,
                    const float* __restrict__ wmu, const float* __restrict__ bmu,
                    float* __restrict__ out)
{
    extern __shared__ char smraw[];
    Smem& sm = *reinterpret_cast<Smem*>(smraw);

    const int t    = threadIdx.x;
    const int lane = t & 31;
    // GEMM thread tile: 8 agents (m) x 8 neurons (n) per thread.
    const int mb = (lane & 7) << 3;                         // m base: 0..56
    const int nb = ((t >> 5) << 5) + ((lane >> 3) << 3);    // n base: 0..248

    // ---- load resident weights into smem --------------------------------
    for (int i = t; i < 13 * HD; i += NT) sm.W1s[i] = w1[i];
    for (int i = t; i < HD; i += NT) {
        sm.b1s[i] = b1[i]; sm.b2s[i] = b2[i]; sm.b3s[i] = b3[i];
    }
    for (int i = t; i < 2 * HD; i += NT) {
        // wmu global layout (256,2): wmu[k*2+d] -> wmuT[d*256+k]
        sm.wmuT[(i & 1) * HD + (i >> 1)] = wmu[i];
    }
    if (t < 2) sm.bmus[t] = bmu[t];

    // ---- per-agent state (threads 0..63) --------------------------------
    const int gid = blockIdx.x * AG + t;
    float px = 0.f, py = 0.f, wx = 0.f, wy = 0.f;
    float mxs = -INFINITY, ss = 0.f;   // online LSE for -8*safe_margin
    float mxr = -INFINITY, sr = 0.f;   // online LSE for  8*reach_margin
    if (t < AG) {
        px = pos0[gid * 2];  py = pos0[gid * 2 + 1];
        wx = wind[gid * 2];  wy = wind[gid * 2 + 1];
    }
    __syncthreads();

    for (int step = 0; step < NSTEP; ++step) {
        // ---------------- observe (one thread per agent) -----------------
        if (t < AG) {
            sm.Obs[0 * AG + t] = px * 0.1f;
            sm.Obs[1 * AG + t] = py * 0.1f;
            sm.Obs[2 * AG + t] = (4.0f - px) * 0.1f;
            sm.Obs[3 * AG + t] = (3.0f - py) * 0.1f;
            sm.Obs[4 * AG + t] = (1.75f - px) * 0.1f;
            sm.Obs[5 * AG + t] = (1.75f - py) * 0.1f;
            sm.Obs[6 * AG + t] = (1.75f - px) * 0.1f;
            sm.Obs[7 * AG + t] = (3.75f - py) * 0.1f;
            sm.Obs[8 * AG + t] = (3.75f - px) * 0.1f;
            sm.Obs[9 * AG + t] = (2.0f  - py) * 0.1f;
            {
                float dx = px - 1.75f, dy = py - 1.75f;
                sm.Obs[10 * AG + t] = sqrtf(dx*dx + dy*dy + 1e-9f) - 0.38f;
            }
            {
                float dx = px - 1.75f, dy = py - 3.75f;
                sm.Obs[11 * AG + t] = sqrtf(dx*dx + dy*dy + 1e-9f) - 0.42f;
            }
            {
                float dx = px - 3.75f, dy = py - 2.0f;
                sm.Obs[12 * AG + t] = sqrtf(dx*dx + dy*dy + 1e-9f) - 0.34f;
            }
        }
        __syncthreads();

        float acc[8][8];

        // ---------------- layer 1: 13 -> 256 -----------------------------
        #pragma unroll
        for (int i = 0; i < 8; ++i)
            #pragma unroll
            for (int j = 0; j < 8; ++j) acc[i][j] = 0.f;

        #pragma unroll
        for (int k = 0; k < 13; ++k) {
            const float* Hr = &sm.Obs[k * AG + mb];
            float4 av0 = *(const float4*)Hr;
            float4 av1 = *(const float4*)(Hr + 4);
            float av[8] = {av0.x, av0.y, av0.z, av0.w, av1.x, av1.y, av1.z, av1.w};
            const float* Br = &sm.W1s[k * HD + nb];
            float4 bv0 = *(const float4*)Br;
            float4 bv1 = *(const float4*)(Br + 4);
            float bv[8] = {bv0.x, bv0.y, bv0.z, bv0.w, bv1.x, bv1.y, bv1.z, bv1.w};
            #pragma unroll
            for (int i = 0; i < 8; ++i)
                #pragma unroll
                for (int j = 0; j < 8; ++j)
                    acc[i][j] = fmaf(av[j], bv[i], acc[i][j]);
        }
        // bias + relu, store [n][m]
        #pragma unroll
        for (int i = 0; i < 8; ++i) {
            float bi = sm.b1s[nb + i];
            #pragma unroll
            for (int j = 0; j < 8; ++j)
                sm.Hbuf[(nb + i) * AG + mb + j] = fmaxf(acc[i][j] + bi, 0.f);
        }
        __syncthreads();

        // ---------------- layers 2 & 3: 256 -> 256 (in-place) ------------
        for (int l = 0; l < 2; ++l) {
            const float4* Wg4  = (const float4*)(l ? w3 : w2);
            const float*  bias = l ? sm.b3s : sm.b2s;

            #pragma unroll
            for (int i = 0; i < 8; ++i)
                #pragma unroll
                for (int j = 0; j < 8; ++j) acc[i][j] = 0.f;

            // register prefetch of first tile
            float4 pf0 = Wg4[t], pf1 = Wg4[t + 256], pf2 = Wg4[t + 512], pf3 = Wg4[t + 768];

            for (int kt = 0; kt < HD; kt += TK) {
                __syncthreads();                 // prior tile fully consumed
                float4* Wt4 = (float4*)sm.Wt;
                Wt4[t] = pf0; Wt4[t + 256] = pf1; Wt4[t + 512] = pf2; Wt4[t + 768] = pf3;
                __syncthreads();
                if (kt + TK < HD) {
                    int base = (kt + TK) * (HD / 4);
                    pf0 = Wg4[base + t];       pf1 = Wg4[base + t + 256];
                    pf2 = Wg4[base + t + 512]; pf3 = Wg4[base + t + 768];
                }
                #pragma unroll
                for (int kk = 0; kk < TK; ++kk) {
                    const float* Hr = &sm.Hbuf[(kt + kk) * AG + mb];
                    float4 av0 = *(const float4*)Hr;
                    float4 av1 = *(const float4*)(Hr + 4);
                    float av[8] = {av0.x, av0.y, av0.z, av0.w, av1.x, av1.y, av1.z, av1.w};
                    const float* Br = &sm.Wt[kk * HD + nb];
                    float4 bv0 = *(const float4*)Br;
                    float4 bv1 = *(const float4*)(Br + 4);
                    float bv[8] = {bv0.x, bv0.y, bv0.z, bv0.w, bv1.x, bv1.y, bv1.z, bv1.w};
                    #pragma unroll
                    for (int i = 0; i < 8; ++i)
                        #pragma unroll
                        for (int j = 0; j < 8; ++j)
                            acc[i][j] = fmaf(av[j], bv[i], acc[i][j]);
                }
            }
            __syncthreads();                     // all reads of Hbuf done
            #pragma unroll
            for (int i = 0; i < 8; ++i) {
                float bi = bias[nb + i];
                #pragma unroll
                for (int j = 0; j < 8; ++j)
                    sm.Hbuf[(nb + i) * AG + mb + j] = fmaxf(acc[i][j] + bi, 0.f);
            }
            __syncthreads();
        }

        // ---------------- output layer: 256 -> 2, clip -------------------
        if (t < 2 * AG) {
            const int d = t >> 6, m = t & 63;
            float s = sm.bmus[d];
            const float* wr = &sm.wmuT[d * HD];
            #pragma unroll 8
            for (int k = 0; k < HD; ++k)
                s = fmaf(wr[k], sm.Hbuf[k * AG + m], s);
            sm.act[d * AG + m] = clampf(s, -1.f, 1.f);
        }
        __syncthreads();

        // ---------------- integrate + margins (one thread per agent) -----
        if (t < AG) {
            float ax = sm.act[t], ay = sm.act[AG + t];
            float vx = 2.f * ax + wx, vy = 2.f * ay + wy;
            #pragma unroll
            for (int s_ = 0; s_ < 4; ++s_) {
                px = clampf(px + 0.0625f * vx, -4.f, 10.f);
                py = clampf(py + 0.0625f * vy, -4.f, 10.f);
            }
            // clearances at post-step position
            float d0x = px - 1.75f, d0y = py - 1.75f;
            float c0 = sqrtf(d0x*d0x + d0y*d0y + 1e-9f) - 0.38f;
            float d1x = px - 1.75f, d1y = py - 3.75f;
            float c1 = sqrtf(d1x*d1x + d1y*d1y + 1e-9f) - 0.42f;
            float d2x = px - 3.75f, d2y = py - 2.0f;
            float c2 = sqrtf(d2x*d2x + d2y*d2y + 1e-9f) - 0.34f;
            // spatial smooth-min, beta=50, stable
            float x0 = -50.f * c0, x1 = -50.f * c1, x2 = -50.f * c2;
            float mM = fmaxf(x0, fmaxf(x1, x2));
            float safe = -(mM + logf(expf(x0 - mM) + expf(x1 - mM) + expf(x2 - mM))) * 0.02f;
            // temporal Always(safe): online LSE of -8*safe
            float xs = -8.f * safe;
            if (xs > mxs) { ss = ss * expf(mxs - xs) + 1.f; mxs = xs; }
            else          { ss += expf(xs - mxs); }
            // Eventually(reach): online LSE of 8*(tol - goal_dist)
            float gx = px - 4.f, gy = py - 3.f;
            float gdist = sqrtf(gx*gx + gy*gy + 1e-9f);
            float xr = 8.f * (0.45f - gdist);
            if (xr > mxr) { sr = sr * expf(mxr - xr) + 1.f; mxr = xr; }
            else          { sr += expf(xr - mxr); }
        }
        // no trailing sync needed: only t<AG touch Obs before the next sync
    }

    // ---- final STREL And(·,·) -------------------------------------------
    if (t < AG) {
        float rho_safe  = -(mxs + logf(ss)) * 0.125f;
        float rho_reach =  (mxr + logf(sr)) * 0.125f;
        float xa = -8.f * rho_safe, xb = -8.f * rho_reach;
        float mm = fmaxf(xa, xb);
        float rho = -(mm + logf(expf(xa - mm) + expf(xb - mm))) * 0.125f;
        out[gid] = rho;
    }
}

extern "C" void kernel_launch(void* const* d_in, const int* in_sizes, int n_in,
                              void* d_out, int out_size)
{
    (void)in_sizes; (void)n_in; (void)out_size;
    const float* pos0 = (const float*)d_in[0];
    const float* wind = (const float*)d_in[1];
    const float* w1   = (const float*)d_in[2];
    const float* b1   = (const float*)d_in[3];
    const float* w2   = (const float*)d_in[4];
    const float* b2   = (const float*)d_in[5];
    const float* w3   = (const float*)d_in[6];
    const float* b3   = (const float*)d_in[7];
    const float* wmu  = (const float*)d_in[8];
    const float* bmu  = (const float*)d_in[9];
    float* out = (float*)d_out;

    const int smem = (int)sizeof(Smem);
    cudaFuncSetAttribute(rollout_kernel,
                         cudaFuncAttributeMaxDynamicSharedMemorySize, smem);
    rollout_kernel<<<32768 / AG, NT, smem>>>(pos0, wind, w1, b1, w2, b2,
                                             w3, b3, wmu, bmu, out);
}